// round 6
// baseline (speedup 1.0000x reference)
#include <cuda_runtime.h>
#include <cuda_fp16.h>
#include <cuda_bf16.h>
#include <cstdint>

// Problem constants
#define IN_F    4096
#define OUT_F   11008
#define M_ROWS  4096
#define NGROUPS 32

// Scratch (no cudaMalloc allowed)
__device__ __half g_Xh[(size_t)M_ROWS * IN_F];    // fp16 x
__device__ __half g_Wh[(size_t)OUT_F * IN_F];     // fp16 dequant W, [n][k]
__device__ float  g_scales[NGROUPS * OUT_F];
__device__ int    g_bad_f16;
__device__ int    g_bad_bf16;

// ---------------------------------------------------------------------------
// scales dtype probe (unchanged from passing rounds)
// ---------------------------------------------------------------------------
__global__ void probe_init() { g_bad_f16 = 0; g_bad_bf16 = 0; }

__global__ void probe_kernel(const void* __restrict__ scales) {
    int i = blockIdx.x * blockDim.x + threadIdx.x;
    if (i >= 176128) return;
    float vf = __half2float(((const __half*)scales)[i]);
    if (!(vf >= 0.0f && vf < 1.0f)) atomicExch(&g_bad_f16, 1);
    float vb = __bfloat162float(((const __nv_bfloat16*)scales)[i]);
    if (!(vb >= 0.0f && vb < 1.0f)) atomicExch(&g_bad_bf16, 1);
}

__global__ void cvt_scales(const void* __restrict__ scales) {
    int i = blockIdx.x * blockDim.x + threadIdx.x;
    if (i >= NGROUPS * OUT_F) return;
    float v;
    if (!g_bad_f16)       v = __half2float(((const __half*)scales)[i]);
    else if (!g_bad_bf16) v = __bfloat162float(((const __nv_bfloat16*)scales)[i]);
    else                  v = ((const float*)scales)[i];
    g_scales[i] = v;
}

// ---------------------------------------------------------------------------
// x (fp32) -> g_Xh (fp16)
// ---------------------------------------------------------------------------
__global__ void cvt_kernel(const float* __restrict__ x) {
    int idx = (blockIdx.x * blockDim.x + threadIdx.x) * 8;
    float4 f0 = *reinterpret_cast<const float4*>(x + idx);
    float4 f1 = *reinterpret_cast<const float4*>(x + idx + 4);
    __align__(16) __half2 h[4];
    h[0] = __floats2half2_rn(f0.x, f0.y);
    h[1] = __floats2half2_rn(f0.z, f0.w);
    h[2] = __floats2half2_rn(f1.x, f1.y);
    h[3] = __floats2half2_rn(f1.z, f1.w);
    *reinterpret_cast<uint4*>(g_Xh + idx) = *reinterpret_cast<const uint4*>(h);
}

// ---------------------------------------------------------------------------
// Dequant pre-pass (unchanged): qweight int4 -> g_Wh fp16 [n][k]
// ---------------------------------------------------------------------------
__global__ __launch_bounds__(256) void dequant_kernel(
    const int* __restrict__ qweight, const int* __restrict__ qzeros)
{
    const int lane = threadIdx.x;
    const int n    = blockIdx.y * 8 + threadIdx.y;
    const int qrow0 = blockIdx.x * 128 + lane * 4;
    const int g = qrow0 >> 4;

    const int z = (qzeros[g * (OUT_F / 8) + (n >> 3)] >> ((n & 7) * 4)) & 15;
    const __half s  = __float2half(g_scales[g * OUT_F + n]);
    const __half2 s2 = __half2half2(s);
    const __half2 mz2 = __half2half2(__float2half((float)(1024 + z)));

    __half* dst = g_Wh + (size_t)n * IN_F + qrow0 * 8;

    #pragma unroll
    for (int i = 0; i < 4; i++) {
        const uint32_t q = (uint32_t)qweight[(size_t)(qrow0 + i) * OUT_F + n];
        uint32_t t0 = ( q         & 0x000F000Fu) | 0x64006400u;
        uint32_t t1 = ((q >> 4)   & 0x000F000Fu) | 0x64006400u;
        uint32_t t2 = ((q >> 8)   & 0x000F000Fu) | 0x64006400u;
        uint32_t t3 = ((q >> 12)  & 0x000F000Fu) | 0x64006400u;
        __half2 p0 = __hmul2(__hsub2(*(__half2*)&t0, mz2), s2);
        __half2 p1 = __hmul2(__hsub2(*(__half2*)&t1, mz2), s2);
        __half2 p2 = __hmul2(__hsub2(*(__half2*)&t2, mz2), s2);
        __half2 p3 = __hmul2(__hsub2(*(__half2*)&t3, mz2), s2);
        uint32_t u0 = *(uint32_t*)&p0, u1 = *(uint32_t*)&p1;
        uint32_t u2 = *(uint32_t*)&p2, u3 = *(uint32_t*)&p3;
        uint4 o;
        o.x = __byte_perm(u0, u1, 0x5410);
        o.y = __byte_perm(u2, u3, 0x5410);
        o.z = __byte_perm(u0, u1, 0x7632);
        o.w = __byte_perm(u2, u3, 0x7632);
        *reinterpret_cast<uint4*>(dst + i * 8) = o;
    }
}

// ---------------------------------------------------------------------------
// HGEMM (mma.sync): CTA 128x256, BK=32, 4-stage cp.async, 8 warps (2m x 4n),
// warp tile 64x64 (1.0 smem-wavefront per MMA). XOR-swizzled smem.
// ---------------------------------------------------------------------------
constexpr int BM  = 128;
constexpr int BN  = 256;
constexpr int BK  = 32;
constexpr int STG = 4;
constexpr int NIT = IN_F / BK;            // 128
constexpr int A_BYTES = BM * BK * 2;      // 8KB
constexpr int B_BYTES = BN * BK * 2;      // 16KB
constexpr int STAGE_BYTES = A_BYTES + B_BYTES;          // 24KB
constexpr int GEMM_SMEM = STG * STAGE_BYTES;            // 96KB

__device__ __forceinline__ uint32_t smem_u32(const void* p) {
    uint32_t a;
    asm("{ .reg .u64 t; cvta.to.shared.u64 t, %1; cvt.u32.u64 %0, t; }"
        : "=r"(a) : "l"(p));
    return a;
}
// byte offset of (row, 8-half chunk ch) within a tile, 64B rows, XOR swizzle
__device__ __forceinline__ uint32_t sw_byte(int row, int ch) {
    return (uint32_t)(row * 64 + ((ch ^ ((row >> 1) & 3)) << 4));
}

__global__ __launch_bounds__(256, 1) void gemm_kernel(
    const float* __restrict__ bias, float* __restrict__ out)
{
    extern __shared__ char smem[];
    const uint32_t sbase = smem_u32(smem);

    const int tid  = threadIdx.x;
    const int lane = tid & 31;
    const int warp = tid >> 5;
    const int warp_m = warp & 1;      // 2 m-warps
    const int warp_n = warp >> 1;     // 4 n-warps

    // grid: m fastest -> A (32MB) becomes L2 resident across n-bands
    const int pid_m = blockIdx.x & 31;       // 32
    const int pid_n = blockIdx.x >> 5;       // 43
    const int m_base = pid_m * BM;
    const int n_base = pid_n * BN;

    float acc[4][8][4];
    #pragma unroll
    for (int mi = 0; mi < 4; mi++)
        #pragma unroll
        for (int ni = 0; ni < 8; ni++)
            #pragma unroll
            for (int r = 0; r < 4; r++) acc[mi][ni][r] = 0.f;

    // producer: 1536 16B copies (A 512, B 1024), 6 per thread
    auto produce = [&](int cc) {
        const uint32_t st = sbase + (cc % STG) * STAGE_BYTES;
        const int k0 = cc * BK;
        #pragma unroll
        for (int i = 0; i < 6; i++) {
            int id = tid + i * 256;           // 0..1535
            if (id < 512) {
                int row = id >> 2, ch = id & 3;
                const __half* src = g_Xh + (size_t)(m_base + row) * IN_F + k0 + ch * 8;
                asm volatile("cp.async.cg.shared.global [%0], [%1], 16;\n"
                             :: "r"(st + sw_byte(row, ch)), "l"(src));
            } else {
                int idb = id - 512;
                int row = idb >> 2, ch = idb & 3;
                const __half* src = g_Wh + (size_t)(n_base + row) * IN_F + k0 + ch * 8;
                asm volatile("cp.async.cg.shared.global [%0], [%1], 16;\n"
                             :: "r"(st + A_BYTES + sw_byte(row, ch)), "l"(src));
            }
        }
        asm volatile("cp.async.commit_group;\n");
    };

    auto compute = [&](int cc) {
        const uint32_t st = sbase + (cc % STG) * STAGE_BYTES;
        #pragma unroll
        for (int ks = 0; ks < 2; ks++) {
            const int kc = ks * 2;
            uint32_t a[4][4], b[8][2];
            #pragma unroll
            for (int mi = 0; mi < 4; mi++) {
                int row = warp_m * 64 + mi * 16 + (lane & 15);
                int ch  = kc + (lane >> 4);
                uint32_t addr = st + sw_byte(row, ch);
                asm volatile(
                    "ldmatrix.sync.aligned.m8n8.x4.shared.b16 {%0,%1,%2,%3}, [%4];"
                    : "=r"(a[mi][0]), "=r"(a[mi][1]), "=r"(a[mi][2]), "=r"(a[mi][3])
                    : "r"(addr));
            }
            #pragma unroll
            for (int nt = 0; nt < 4; nt++) {  // x4 covers two n8 tiles
                int row = warp_n * 64 + nt * 16 + ((lane >> 4) << 3) + (lane & 7);
                int ch  = kc + ((lane >> 3) & 1);
                uint32_t addr = st + A_BYTES + sw_byte(row, ch);
                asm volatile(
                    "ldmatrix.sync.aligned.m8n8.x4.shared.b16 {%0,%1,%2,%3}, [%4];"
                    : "=r"(b[2*nt][0]), "=r"(b[2*nt][1]),
                      "=r"(b[2*nt+1][0]), "=r"(b[2*nt+1][1])
                    : "r"(addr));
            }
            #pragma unroll
            for (int mi = 0; mi < 4; mi++)
                #pragma unroll
                for (int ni = 0; ni < 8; ni++)
                    asm volatile(
                        "mma.sync.aligned.m16n8k16.row.col.f32.f16.f16.f32 "
                        "{%0,%1,%2,%3}, {%4,%5,%6,%7}, {%8,%9}, {%0,%1,%2,%3};"
                        : "+f"(acc[mi][ni][0]), "+f"(acc[mi][ni][1]),
                          "+f"(acc[mi][ni][2]), "+f"(acc[mi][ni][3])
                        : "r"(a[mi][0]), "r"(a[mi][1]), "r"(a[mi][2]), "r"(a[mi][3]),
                          "r"(b[ni][0]), "r"(b[ni][1]));
        }
    };

    // prologue: stages 0..2 in flight
    produce(0);
    produce(1);
    produce(2);

    for (int c = 0; c < NIT; c++) {
        // group c complete (committed so far: 3 + c groups, allow 2 pending)
        asm volatile("cp.async.wait_group 2;\n");
        __syncthreads();                       // also: compute(c-1) fully done
        if (c + 3 < NIT) produce(c + 3);
        else asm volatile("cp.async.commit_group;\n");   // keep group count uniform
        compute(c);
    }

    // epilogue
    #pragma unroll
    for (int mi = 0; mi < 4; mi++) {
        int row0 = m_base + warp_m * 64 + mi * 16 + (lane >> 2);
        #pragma unroll
        for (int ni = 0; ni < 8; ni++) {
            int col = n_base + warp_n * 64 + ni * 8 + ((lane & 3) << 1);
            float b0 = bias[col], b1 = bias[col + 1];
            float2 v0 = make_float2(acc[mi][ni][0] + b0, acc[mi][ni][1] + b1);
            float2 v1 = make_float2(acc[mi][ni][2] + b0, acc[mi][ni][3] + b1);
            *reinterpret_cast<float2*>(out + (size_t)row0 * OUT_F + col)       = v0;
            *reinterpret_cast<float2*>(out + (size_t)(row0 + 8) * OUT_F + col) = v1;
        }
    }
}

// ---------------------------------------------------------------------------
extern "C" void kernel_launch(void* const* d_in, const int* in_sizes, int n_in,
                              void* d_out, int out_size)
{
    const void *p_x = nullptr, *p_qw = nullptr, *p_qz = nullptr,
               *p_sc = nullptr, *p_b = nullptr;
    for (int i = 0; i < n_in; i++) {
        switch (in_sizes[i]) {
            case M_ROWS * IN_F:        p_x  = d_in[i]; break;
            case (IN_F / 8) * OUT_F:   p_qw = d_in[i]; break;
            case NGROUPS * (OUT_F/8):  p_qz = d_in[i]; break;
            case NGROUPS * OUT_F:      p_sc = d_in[i]; break;
            case OUT_F:                p_b  = d_in[i]; break;
        }
    }

    probe_init<<<1, 1>>>();
    probe_kernel<<<(176128 + 255) / 256, 256>>>(p_sc);
    cvt_scales<<<(NGROUPS * OUT_F + 255) / 256, 256>>>(p_sc);
    cvt_kernel<<<(M_ROWS * IN_F) / (256 * 8), 256>>>((const float*)p_x);
    dequant_kernel<<<dim3(4, OUT_F / 8), dim3(32, 8)>>>((const int*)p_qw,
                                                        (const int*)p_qz);

    // Not stream-ordered; safe and deterministic on every call (incl. capture).
    cudaFuncSetAttribute(gemm_kernel,
                         cudaFuncAttributeMaxDynamicSharedMemorySize, GEMM_SMEM);

    // grid: 32 m-tiles x 43 n-tiles, m fastest
    gemm_kernel<<<32 * 43, 256, GEMM_SMEM>>>((const float*)p_b, (float*)d_out);
}

// round 7
// speedup vs baseline: 1.2621x; 1.2621x over previous
#include <cuda_runtime.h>
#include <cuda_fp16.h>
#include <cuda_bf16.h>
#include <cstdint>

// Problem constants
#define IN_F    4096
#define OUT_F   11008
#define M_ROWS  4096
#define NGROUPS 32

// Scratch (no cudaMalloc allowed)
__device__ __half g_Xh[(size_t)M_ROWS * IN_F];    // fp16 x
__device__ __half g_Wh[(size_t)OUT_F * IN_F];     // fp16 dequant W, [n][k]
__device__ float  g_scales[NGROUPS * OUT_F];
__device__ int    g_bad_f16;
__device__ int    g_bad_bf16;

// ---------------------------------------------------------------------------
// scales dtype probe (unchanged from passing rounds)
// ---------------------------------------------------------------------------
__global__ void probe_init() { g_bad_f16 = 0; g_bad_bf16 = 0; }

__global__ void probe_kernel(const void* __restrict__ scales) {
    int i = blockIdx.x * blockDim.x + threadIdx.x;
    if (i >= 176128) return;
    float vf = __half2float(((const __half*)scales)[i]);
    if (!(vf >= 0.0f && vf < 1.0f)) atomicExch(&g_bad_f16, 1);
    float vb = __bfloat162float(((const __nv_bfloat16*)scales)[i]);
    if (!(vb >= 0.0f && vb < 1.0f)) atomicExch(&g_bad_bf16, 1);
}

__global__ void cvt_scales(const void* __restrict__ scales) {
    int i = blockIdx.x * blockDim.x + threadIdx.x;
    if (i >= NGROUPS * OUT_F) return;
    float v;
    if (!g_bad_f16)       v = __half2float(((const __half*)scales)[i]);
    else if (!g_bad_bf16) v = __bfloat162float(((const __nv_bfloat16*)scales)[i]);
    else                  v = ((const float*)scales)[i];
    g_scales[i] = v;
}

// ---------------------------------------------------------------------------
// x (fp32) -> g_Xh (fp16)
// ---------------------------------------------------------------------------
__global__ void cvt_kernel(const float* __restrict__ x) {
    int idx = (blockIdx.x * blockDim.x + threadIdx.x) * 8;
    float4 f0 = *reinterpret_cast<const float4*>(x + idx);
    float4 f1 = *reinterpret_cast<const float4*>(x + idx + 4);
    __align__(16) __half2 h[4];
    h[0] = __floats2half2_rn(f0.x, f0.y);
    h[1] = __floats2half2_rn(f0.z, f0.w);
    h[2] = __floats2half2_rn(f1.x, f1.y);
    h[3] = __floats2half2_rn(f1.z, f1.w);
    *reinterpret_cast<uint4*>(g_Xh + idx) = *reinterpret_cast<const uint4*>(h);
}

// ---------------------------------------------------------------------------
// Dequant pre-pass (unchanged): qweight int4 -> g_Wh fp16 [n][k]
// ---------------------------------------------------------------------------
__global__ __launch_bounds__(256) void dequant_kernel(
    const int* __restrict__ qweight, const int* __restrict__ qzeros)
{
    const int lane = threadIdx.x;
    const int n    = blockIdx.y * 8 + threadIdx.y;
    const int qrow0 = blockIdx.x * 128 + lane * 4;
    const int g = qrow0 >> 4;

    const int z = (qzeros[g * (OUT_F / 8) + (n >> 3)] >> ((n & 7) * 4)) & 15;
    const __half s  = __float2half(g_scales[g * OUT_F + n]);
    const __half2 s2 = __half2half2(s);
    const __half2 mz2 = __half2half2(__float2half((float)(1024 + z)));

    __half* dst = g_Wh + (size_t)n * IN_F + qrow0 * 8;

    #pragma unroll
    for (int i = 0; i < 4; i++) {
        const uint32_t q = (uint32_t)qweight[(size_t)(qrow0 + i) * OUT_F + n];
        uint32_t t0 = ( q         & 0x000F000Fu) | 0x64006400u;
        uint32_t t1 = ((q >> 4)   & 0x000F000Fu) | 0x64006400u;
        uint32_t t2 = ((q >> 8)   & 0x000F000Fu) | 0x64006400u;
        uint32_t t3 = ((q >> 12)  & 0x000F000Fu) | 0x64006400u;
        __half2 p0 = __hmul2(__hsub2(*(__half2*)&t0, mz2), s2);
        __half2 p1 = __hmul2(__hsub2(*(__half2*)&t1, mz2), s2);
        __half2 p2 = __hmul2(__hsub2(*(__half2*)&t2, mz2), s2);
        __half2 p3 = __hmul2(__hsub2(*(__half2*)&t3, mz2), s2);
        uint32_t u0 = *(uint32_t*)&p0, u1 = *(uint32_t*)&p1;
        uint32_t u2 = *(uint32_t*)&p2, u3 = *(uint32_t*)&p3;
        uint4 o;
        o.x = __byte_perm(u0, u1, 0x5410);
        o.y = __byte_perm(u2, u3, 0x5410);
        o.z = __byte_perm(u0, u1, 0x7632);
        o.w = __byte_perm(u2, u3, 0x7632);
        *reinterpret_cast<uint4*>(dst + i * 8) = o;
    }
}

// ---------------------------------------------------------------------------
// HGEMM (mma.sync): CTA 128x128, 4 warps (2m x 2n), warp tile 64x64,
// BK=32, 4-stage cp.async, 64KB smem -> 2 CTAs/SM for latency hiding.
// ---------------------------------------------------------------------------
constexpr int BM  = 128;
constexpr int BN  = 128;
constexpr int BK  = 32;
constexpr int STG = 4;
constexpr int NIT = IN_F / BK;            // 128
constexpr int A_BYTES = BM * BK * 2;      // 8KB
constexpr int B_BYTES = BN * BK * 2;      // 8KB
constexpr int STAGE_BYTES = A_BYTES + B_BYTES;          // 16KB
constexpr int GEMM_SMEM = STG * STAGE_BYTES;            // 64KB

__device__ __forceinline__ uint32_t smem_u32(const void* p) {
    uint32_t a;
    asm("{ .reg .u64 t; cvta.to.shared.u64 t, %1; cvt.u32.u64 %0, t; }"
        : "=r"(a) : "l"(p));
    return a;
}
// byte offset of (row, 8-half chunk ch) within a tile, 64B rows, XOR swizzle
__device__ __forceinline__ uint32_t sw_byte(int row, int ch) {
    return (uint32_t)(row * 64 + ((ch ^ ((row >> 1) & 3)) << 4));
}

__global__ __launch_bounds__(128, 2) void gemm_kernel(
    const float* __restrict__ bias, float* __restrict__ out)
{
    extern __shared__ char smem[];
    const uint32_t sbase = smem_u32(smem);

    const int tid  = threadIdx.x;
    const int lane = tid & 31;
    const int warp = tid >> 5;        // 0..3
    const int warp_m = warp & 1;      // 2 m-warps
    const int warp_n = warp >> 1;     // 2 n-warps

    // grid: m fastest -> A (32MB) stays L2 resident across n-bands
    const int pid_m = blockIdx.x & 31;       // 32
    const int pid_n = blockIdx.x >> 5;       // 86
    const int m_base = pid_m * BM;
    const int n_base = pid_n * BN;

    float acc[4][8][4];
    #pragma unroll
    for (int mi = 0; mi < 4; mi++)
        #pragma unroll
        for (int ni = 0; ni < 8; ni++)
            #pragma unroll
            for (int r = 0; r < 4; r++) acc[mi][ni][r] = 0.f;

    // producer: 1024 16B copies (A 512, B 512), 8 per thread
    auto produce = [&](int cc) {
        const uint32_t st = sbase + (cc % STG) * STAGE_BYTES;
        const int k0 = cc * BK;
        #pragma unroll
        for (int i = 0; i < 8; i++) {
            int id = tid + i * 128;           // 0..1023
            if (id < 512) {
                int row = id >> 2, ch = id & 3;
                const __half* src = g_Xh + (size_t)(m_base + row) * IN_F + k0 + ch * 8;
                asm volatile("cp.async.cg.shared.global [%0], [%1], 16;\n"
                             :: "r"(st + sw_byte(row, ch)), "l"(src));
            } else {
                int idb = id - 512;
                int row = idb >> 2, ch = idb & 3;
                const __half* src = g_Wh + (size_t)(n_base + row) * IN_F + k0 + ch * 8;
                asm volatile("cp.async.cg.shared.global [%0], [%1], 16;\n"
                             :: "r"(st + A_BYTES + sw_byte(row, ch)), "l"(src));
            }
        }
        asm volatile("cp.async.commit_group;\n");
    };

    auto compute = [&](int cc) {
        const uint32_t st = sbase + (cc % STG) * STAGE_BYTES;
        #pragma unroll
        for (int ks = 0; ks < 2; ks++) {
            const int kc = ks * 2;
            uint32_t a[4][4], b[8][2];
            #pragma unroll
            for (int mi = 0; mi < 4; mi++) {
                int row = warp_m * 64 + mi * 16 + (lane & 15);
                int ch  = kc + (lane >> 4);
                uint32_t addr = st + sw_byte(row, ch);
                asm volatile(
                    "ldmatrix.sync.aligned.m8n8.x4.shared.b16 {%0,%1,%2,%3}, [%4];"
                    : "=r"(a[mi][0]), "=r"(a[mi][1]), "=r"(a[mi][2]), "=r"(a[mi][3])
                    : "r"(addr));
            }
            #pragma unroll
            for (int nt = 0; nt < 4; nt++) {  // x4 covers two n8 tiles
                int row = warp_n * 64 + nt * 16 + ((lane >> 4) << 3) + (lane & 7);
                int ch  = kc + ((lane >> 3) & 1);
                uint32_t addr = st + A_BYTES + sw_byte(row, ch);
                asm volatile(
                    "ldmatrix.sync.aligned.m8n8.x4.shared.b16 {%0,%1,%2,%3}, [%4];"
                    : "=r"(b[2*nt][0]), "=r"(b[2*nt][1]),
                      "=r"(b[2*nt+1][0]), "=r"(b[2*nt+1][1])
                    : "r"(addr));
            }
            #pragma unroll
            for (int mi = 0; mi < 4; mi++)
                #pragma unroll
                for (int ni = 0; ni < 8; ni++)
                    asm volatile(
                        "mma.sync.aligned.m16n8k16.row.col.f32.f16.f16.f32 "
                        "{%0,%1,%2,%3}, {%4,%5,%6,%7}, {%8,%9}, {%0,%1,%2,%3};"
                        : "+f"(acc[mi][ni][0]), "+f"(acc[mi][ni][1]),
                          "+f"(acc[mi][ni][2]), "+f"(acc[mi][ni][3])
                        : "r"(a[mi][0]), "r"(a[mi][1]), "r"(a[mi][2]), "r"(a[mi][3]),
                          "r"(b[ni][0]), "r"(b[ni][1]));
        }
    };

    // prologue: stages 0..2 in flight
    produce(0);
    produce(1);
    produce(2);

    for (int c = 0; c < NIT; c++) {
        asm volatile("cp.async.wait_group 2;\n");        // group c complete
        __syncthreads();                                 // compute(c-1) done
        if (c + 3 < NIT) produce(c + 3);
        else asm volatile("cp.async.commit_group;\n");   // uniform group count
        compute(c);
    }

    // epilogue
    #pragma unroll
    for (int mi = 0; mi < 4; mi++) {
        int row0 = m_base + warp_m * 64 + mi * 16 + (lane >> 2);
        #pragma unroll
        for (int ni = 0; ni < 8; ni++) {
            int col = n_base + warp_n * 64 + ni * 8 + ((lane & 3) << 1);
            float b0 = bias[col], b1 = bias[col + 1];
            float2 v0 = make_float2(acc[mi][ni][0] + b0, acc[mi][ni][1] + b1);
            float2 v1 = make_float2(acc[mi][ni][2] + b0, acc[mi][ni][3] + b1);
            *reinterpret_cast<float2*>(out + (size_t)row0 * OUT_F + col)       = v0;
            *reinterpret_cast<float2*>(out + (size_t)(row0 + 8) * OUT_F + col) = v1;
        }
    }
}

// ---------------------------------------------------------------------------
extern "C" void kernel_launch(void* const* d_in, const int* in_sizes, int n_in,
                              void* d_out, int out_size)
{
    const void *p_x = nullptr, *p_qw = nullptr, *p_qz = nullptr,
               *p_sc = nullptr, *p_b = nullptr;
    for (int i = 0; i < n_in; i++) {
        switch (in_sizes[i]) {
            case M_ROWS * IN_F:        p_x  = d_in[i]; break;
            case (IN_F / 8) * OUT_F:   p_qw = d_in[i]; break;
            case NGROUPS * (OUT_F/8):  p_qz = d_in[i]; break;
            case NGROUPS * OUT_F:      p_sc = d_in[i]; break;
            case OUT_F:                p_b  = d_in[i]; break;
        }
    }

    probe_init<<<1, 1>>>();
    probe_kernel<<<(176128 + 255) / 256, 256>>>(p_sc);
    cvt_scales<<<(NGROUPS * OUT_F + 255) / 256, 256>>>(p_sc);
    cvt_kernel<<<(M_ROWS * IN_F) / (256 * 8), 256>>>((const float*)p_x);
    dequant_kernel<<<dim3(4, OUT_F / 8), dim3(32, 8)>>>((const int*)p_qw,
                                                        (const int*)p_qz);

    // Not stream-ordered; safe and deterministic on every call (incl. capture).
    cudaFuncSetAttribute(gemm_kernel,
                         cudaFuncAttributeMaxDynamicSharedMemorySize, GEMM_SMEM);

    // grid: 32 m-tiles x 86 n-tiles, m fastest
    gemm_kernel<<<32 * 86, 128, GEMM_SMEM>>>((const float*)p_b, (float*)d_out);
}